// round 1
// baseline (speedup 1.0000x reference)
#include <cuda_runtime.h>

#define Bz 4
#define Cc 256
#define Cii 128
#define Nn 4096
#define KSsplit 16
#define KPB (Nn / KSsplit)   // 256 K per split block

typedef unsigned long long u64;

__device__ __forceinline__ u64 pack2(float lo, float hi) {
    u64 r; asm("mov.b64 %0, {%1,%2};" : "=l"(r) : "f"(lo), "f"(hi)); return r;
}
__device__ __forceinline__ float2 unpack2(u64 v) {
    float2 f; asm("mov.b64 {%0,%1}, %2;" : "=f"(f.x), "=f"(f.y) : "l"(v)); return f;
}
__device__ __forceinline__ u64 fma2(u64 a, u64 b, u64 c) {
    u64 d; asm("fma.rn.f32x2 %0, %1, %2, %3;" : "=l"(d) : "l"(a), "l"(b), "l"(c)); return d;
}

// ---------------- scratch (static device globals; no allocation) -------------
__device__ float g_Rpart[Bz * KSsplit * Cc * Cc];   // 16 MB split-K partials
__device__ float g_R[Bz * Cc * Cc];                 // R = B B^T  per batch
__device__ float g_s[Bz * Cc];                      // row sums of b image
__device__ float g_gs[Bz * Cii];                    // g_w @ s
__device__ float g_ps2[Bz * Cii];                   // phi_w @ s + N*phi_b
__device__ float g_U[Bz * Cii * Cc];                // g_w @ R
__device__ float g_S[Bz * Cii * Cii];               // G Phi^T
__device__ float g_T[Bz * Cc * Cii];                // W_w @ S / N
__device__ float g_Q[Bz * Cc * Cc];                 // T @ theta_w
__device__ float g_dp[Bz * Cc];                     // folded bias (BN included)
__device__ float g_alpha[Cc];                       // BN scale

// ---------------- row sums of b: s[b][c] = sum_n b[b,c,n] --------------------
__global__ __launch_bounds__(128) void k_rowsum(const float* __restrict__ bimg) {
    int bc = blockIdx.x;  // b*Cc + c
    const float* row = bimg + (size_t)bc * Nn;
    float sum = 0.f;
    for (int i = threadIdx.x; i < Nn; i += 128) sum += row[i];
    #pragma unroll
    for (int o = 16; o > 0; o >>= 1) sum += __shfl_down_sync(0xffffffffu, sum, o);
    __shared__ float red[4];
    if ((threadIdx.x & 31) == 0) red[threadIdx.x >> 5] = sum;
    __syncthreads();
    if (threadIdx.x == 0) g_s[bc] = red[0] + red[1] + red[2] + red[3];
}

// ---------------- gs = g_w @ s ; ps2 = phi_w @ s + N*phi_b -------------------
__global__ __launch_bounds__(256) void k_gsps(const float* __restrict__ gw,
                                              const float* __restrict__ phiw,
                                              const float* __restrict__ phib) {
    int b = blockIdx.x;
    int tid = threadIdx.x;
    __shared__ float ssh[Cc];
    ssh[tid] = g_s[b * Cc + tid];
    __syncthreads();
    if (tid < Cii) {
        float acc = 0.f;
        for (int c = 0; c < Cc; c++) acc += gw[tid * Cc + c] * ssh[c];
        g_gs[b * Cii + tid] = acc;
    } else {
        int i = tid - Cii;
        float acc = 0.f;
        for (int c = 0; c < Cc; c++) acc += phiw[i * Cc + c] * ssh[c];
        g_ps2[b * Cii + i] = acc + (float)Nn * phib[i];
    }
}

// ---------------- split-K SYRK: R_part[b,ks] = B[:,kslice] B[:,kslice]^T -----
// grid (4, 2, Bz*KSsplit); tile 64(i) x 128(j); micro 4x8 via f32x2
__global__ __launch_bounds__(256, 2) void k_syrk(const float* __restrict__ bimg) {
    int ti = blockIdx.x * 64;
    int tj = blockIdx.y * 128;
    int bz = blockIdx.z >> 4;
    int ks = blockIdx.z & (KSsplit - 1);
    const float* Bb = bimg + (size_t)bz * Cc * Nn;
    __shared__ __align__(16) float Asm[32][65];
    __shared__ __align__(16) float Bsn[32][132];
    int tid = threadIdx.x;
    int tx = tid & 15, ty = tid >> 4;
    u64 acc[4][4];
    #pragma unroll
    for (int i = 0; i < 4; i++)
        #pragma unroll
        for (int j = 0; j < 4; j++) acc[i][j] = 0ull;

    int k0 = ks * KPB;
    for (int kk = 0; kk < KPB; kk += 32) {
        #pragma unroll
        for (int l = 0; l < 8; l++) {          // A tile 64x32, transposed store
            int idx = tid + l * 256;
            int r = idx >> 5, k = idx & 31;
            Asm[k][r] = Bb[(size_t)(ti + r) * Nn + k0 + kk + k];
        }
        #pragma unroll
        for (int l = 0; l < 16; l++) {         // B tile 128x32, transposed store
            int idx = tid + l * 256;
            int r = idx >> 5, k = idx & 31;
            Bsn[k][r] = Bb[(size_t)(tj + r) * Nn + k0 + kk + k];
        }
        __syncthreads();
        #pragma unroll
        for (int k = 0; k < 32; k++) {
            u64 ad[4], bv[4];
            #pragma unroll
            for (int i = 0; i < 4; i++) { float a = Asm[k][ty * 4 + i]; ad[i] = pack2(a, a); }
            #pragma unroll
            for (int j = 0; j < 4; j++) bv[j] = *(const u64*)&Bsn[k][tx * 8 + j * 2];
            #pragma unroll
            for (int i = 0; i < 4; i++)
                #pragma unroll
                for (int j = 0; j < 4; j++) acc[i][j] = fma2(ad[i], bv[j], acc[i][j]);
        }
        __syncthreads();
    }
    float* Rp = g_Rpart + (size_t)(bz * KSsplit + ks) * Cc * Cc;
    #pragma unroll
    for (int i = 0; i < 4; i++) {
        int ci = ti + ty * 4 + i;
        float2 p0 = unpack2(acc[i][0]), p1 = unpack2(acc[i][1]);
        float2 p2 = unpack2(acc[i][2]), p3 = unpack2(acc[i][3]);
        float4 v0 = make_float4(p0.x, p0.y, p1.x, p1.y);
        float4 v1 = make_float4(p2.x, p2.y, p3.x, p3.y);
        float* dst = Rp + (size_t)ci * Cc + tj + tx * 8;
        *(float4*)dst = v0;
        *(float4*)(dst + 4) = v1;
    }
}

// ---------------- reduce split-K partials ------------------------------------
__global__ __launch_bounds__(256) void k_reduceR() {
    int e = blockIdx.x * 256 + threadIdx.x;        // < Bz*Cc*Cc
    int b = e >> 16;
    int r = e & 65535;
    float sum = 0.f;
    #pragma unroll
    for (int ks = 0; ks < KSsplit; ks++)
        sum += g_Rpart[(size_t)(b * KSsplit + ks) * Cc * Cc + r];
    g_R[e] = sum;
}

// ---------------- generic small batched GEMM (32x32 tiles) -------------------
// C[b] = scale * A[b](MxK) @ B[b]  (+ optional two rank-1 terms)
// B stored [K,N] if BT==0 else [N,K]
__global__ __launch_bounds__(256) void k_gemm32(
    const float* __restrict__ A, long long sA,
    const float* __restrict__ B, long long sB,
    float* __restrict__ C, long long sC,
    int M, int N, int K, int BT, float scale,
    const float* __restrict__ r1a, long long s1a,
    const float* __restrict__ r1b, long long s1b,
    const float* __restrict__ r2a, long long s2a,
    const float* __restrict__ r2b, long long s2b)
{
    int m0 = blockIdx.x * 32, n0 = blockIdx.y * 32, bz = blockIdx.z;
    A += (size_t)bz * sA; B += (size_t)bz * sB; C += (size_t)bz * sC;
    __shared__ float As[32][33], Bs[32][33];
    int tid = threadIdx.x, tx = tid & 15, ty = tid >> 4;
    float acc00 = 0.f, acc01 = 0.f, acc10 = 0.f, acc11 = 0.f;
    for (int k0 = 0; k0 < K; k0 += 32) {
        #pragma unroll
        for (int l = 0; l < 4; l++) {
            int idx = tid + l * 256;
            int r = idx >> 5, k = idx & 31;
            As[k][r] = A[(size_t)(m0 + r) * K + k0 + k];
            if (!BT) Bs[r][k] = B[(size_t)(k0 + r) * N + n0 + k];
            else     Bs[k][r] = B[(size_t)(n0 + r) * K + k0 + k];
        }
        __syncthreads();
        #pragma unroll
        for (int k = 0; k < 32; k++) {
            float a0 = As[k][ty * 2], a1 = As[k][ty * 2 + 1];
            float b0 = Bs[k][tx * 2], b1 = Bs[k][tx * 2 + 1];
            acc00 += a0 * b0; acc01 += a0 * b1;
            acc10 += a1 * b0; acc11 += a1 * b1;
        }
        __syncthreads();
    }
    float e[2][2] = {{acc00, acc01}, {acc10, acc11}};
    #pragma unroll
    for (int ii = 0; ii < 2; ii++)
        #pragma unroll
        for (int jj = 0; jj < 2; jj++) {
            int m = m0 + ty * 2 + ii, n = n0 + tx * 2 + jj;
            float v = e[ii][jj] * scale;
            if (r1a)
                v += r1a[(size_t)bz * s1a + m] * r1b[(size_t)bz * s1b + n]
                   + r2a[(size_t)bz * s2a + m] * r2b[(size_t)bz * s2b + n];
            C[(size_t)m * N + n] = v;
        }
}

// ---------------- fold theta_b + BN into per-(b,c) bias & alpha --------------
__global__ __launch_bounds__(256) void k_dvec(
    const float* __restrict__ theta_b, const float* __restrict__ gamma,
    const float* __restrict__ beta, const float* __restrict__ mean,
    const float* __restrict__ var)
{
    int b = blockIdx.x, c = threadIdx.x;
    const float* Trow = g_T + ((size_t)b * Cc + c) * Cii;
    float d = 0.f;
    for (int i = 0; i < Cii; i++) d += Trow[i] * theta_b[i];
    float al = gamma[c] * rsqrtf(var[c] + 1e-5f);
    g_dp[b * Cc + c] = al * (d - mean[c]) + beta[c];
    if (b == 0) g_alpha[c] = al;
}

// ---------------- final: out[b] = alpha .* (Q[b] @ A[b]) + dp ----------------
// grid (4, 32, Bz); tile 64(c) x 128(n); K=256; micro 4x8 via f32x2
__global__ __launch_bounds__(256, 2) void k_out(const float* __restrict__ aimg,
                                                float* __restrict__ out)
{
    int tc = blockIdx.x * 64;
    int tn = blockIdx.y * 128;
    int bz = blockIdx.z;
    const float* Ab = aimg + (size_t)bz * Cc * Nn;
    const float* Qb = g_Q + (size_t)bz * Cc * Cc;
    __shared__ __align__(16) float Qs[32][65];
    __shared__ __align__(16) float Asn[32][132];
    int tid = threadIdx.x;
    int tx = tid & 15, ty = tid >> 4;
    u64 acc[4][4];
    #pragma unroll
    for (int i = 0; i < 4; i++)
        #pragma unroll
        for (int j = 0; j < 4; j++) acc[i][j] = 0ull;

    for (int k0 = 0; k0 < Cc; k0 += 32) {
        #pragma unroll
        for (int l = 0; l < 8; l++) {           // Q tile 64x32, transposed
            int idx = tid + l * 256;
            int r = idx >> 5, k = idx & 31;
            Qs[k][r] = Qb[(size_t)(tc + r) * Cc + k0 + k];
        }
        #pragma unroll
        for (int l = 0; l < 4; l++) {           // A tile 32x128, natural (vec4)
            int idx = tid + l * 256;
            int kr = idx >> 5;
            int nq = (idx & 31) * 4;
            *(float4*)&Asn[kr][nq] = *(const float4*)&Ab[(size_t)(k0 + kr) * Nn + tn + nq];
        }
        __syncthreads();
        #pragma unroll
        for (int k = 0; k < 32; k++) {
            u64 qd[4], av[4];
            #pragma unroll
            for (int i = 0; i < 4; i++) { float q = Qs[k][ty * 4 + i]; qd[i] = pack2(q, q); }
            #pragma unroll
            for (int j = 0; j < 4; j++) av[j] = *(const u64*)&Asn[k][tx * 8 + j * 2];
            #pragma unroll
            for (int i = 0; i < 4; i++)
                #pragma unroll
                for (int j = 0; j < 4; j++) acc[i][j] = fma2(qd[i], av[j], acc[i][j]);
        }
        __syncthreads();
    }
    float* outb = out + (size_t)bz * Cc * Nn;
    #pragma unroll
    for (int i = 0; i < 4; i++) {
        int c = tc + ty * 4 + i;
        float al = g_alpha[c];
        float dpv = g_dp[bz * Cc + c];
        float2 p0 = unpack2(acc[i][0]), p1 = unpack2(acc[i][1]);
        float2 p2 = unpack2(acc[i][2]), p3 = unpack2(acc[i][3]);
        float4 v0 = make_float4(al * p0.x + dpv, al * p0.y + dpv, al * p1.x + dpv, al * p1.y + dpv);
        float4 v1 = make_float4(al * p2.x + dpv, al * p2.y + dpv, al * p3.x + dpv, al * p3.y + dpv);
        float* dst = outb + (size_t)c * Nn + tn + tx * 8;
        *(float4*)dst = v0;
        *(float4*)(dst + 4) = v1;
    }
}

// -----------------------------------------------------------------------------
extern "C" void kernel_launch(void* const* d_in, const int* in_sizes, int n_in,
                              void* d_out, int out_size) {
    (void)in_sizes; (void)n_in; (void)out_size;
    const float* a       = (const float*)d_in[0];
    const float* bimg    = (const float*)d_in[1];
    const float* theta_w = (const float*)d_in[2];
    const float* theta_b = (const float*)d_in[3];
    const float* phi_w   = (const float*)d_in[4];
    const float* phi_b   = (const float*)d_in[5];
    const float* g_wp    = (const float*)d_in[6];
    const float* g_bp    = (const float*)d_in[7];
    const float* W_wp    = (const float*)d_in[8];
    const float* gamma   = (const float*)d_in[9];
    const float* beta    = (const float*)d_in[10];
    const float* mean    = (const float*)d_in[11];
    const float* var     = (const float*)d_in[12];

    float *pR, *pU, *pS, *pT, *pQ, *pGs, *pPs2;
    cudaGetSymbolAddress((void**)&pR,   g_R);
    cudaGetSymbolAddress((void**)&pU,   g_U);
    cudaGetSymbolAddress((void**)&pS,   g_S);
    cudaGetSymbolAddress((void**)&pT,   g_T);
    cudaGetSymbolAddress((void**)&pQ,   g_Q);
    cudaGetSymbolAddress((void**)&pGs,  g_gs);
    cudaGetSymbolAddress((void**)&pPs2, g_ps2);

    k_rowsum<<<Bz * Cc, 128>>>(bimg);
    k_gsps<<<Bz, 256>>>(g_wp, phi_w, phi_b);
    k_syrk<<<dim3(4, 2, Bz * KSsplit), 256>>>(bimg);
    k_reduceR<<<(Bz * Cc * Cc) / 256, 256>>>();

    // U[b] = g_w @ R[b]                         [128,256] = [128,256]x[256,256]
    k_gemm32<<<dim3(Cii / 32, Cc / 32, Bz), 256>>>(
        g_wp, 0, pR, (long long)Cc * Cc, pU, (long long)Cii * Cc,
        Cii, Cc, Cc, 0, 1.f,
        nullptr, 0, nullptr, 0, nullptr, 0, nullptr, 0);
    // S[b] = U[b] @ phi_w^T + gs*phib^T + gb*ps2^T         [128,128]
    k_gemm32<<<dim3(Cii / 32, Cii / 32, Bz), 256>>>(
        pU, (long long)Cii * Cc, phi_w, 0, pS, (long long)Cii * Cii,
        Cii, Cii, Cc, 1, 1.f,
        pGs, Cii, phi_b, 0, g_bp, 0, pPs2, Cii);
    // T[b] = W_w @ S[b] / N                     [256,128]
    k_gemm32<<<dim3(Cc / 32, Cii / 32, Bz), 256>>>(
        W_wp, 0, pS, (long long)Cii * Cii, pT, (long long)Cc * Cii,
        Cc, Cii, Cii, 0, 1.f / (float)Nn,
        nullptr, 0, nullptr, 0, nullptr, 0, nullptr, 0);
    // Q[b] = T[b] @ theta_w                     [256,256]
    k_gemm32<<<dim3(Cc / 32, Cc / 32, Bz), 256>>>(
        pT, (long long)Cc * Cii, theta_w, 0, pQ, (long long)Cc * Cc,
        Cc, Cc, Cii, 0, 1.f,
        nullptr, 0, nullptr, 0, nullptr, 0, nullptr, 0);

    k_dvec<<<Bz, 256>>>(theta_b, gamma, beta, mean, var);
    k_out<<<dim3(Cc / 64, Nn / 128, Bz), 256>>>(a, (float*)d_out);
}

// round 3
// speedup vs baseline: 1.2972x; 1.2972x over previous
#include <cuda_runtime.h>

#define Bz 4
#define Cc 256
#define Cii 128
#define Nn 4096
#define KSsplit 16
#define KPB (Nn / KSsplit)   // 256 K per split block

typedef unsigned long long u64;

__device__ __forceinline__ u64 pack2(float lo, float hi) {
    u64 r; asm("mov.b64 %0, {%1,%2};" : "=l"(r) : "f"(lo), "f"(hi)); return r;
}
__device__ __forceinline__ float2 unpack2(u64 v) {
    float2 f; asm("mov.b64 {%0,%1}, %2;" : "=f"(f.x), "=f"(f.y) : "l"(v)); return f;
}
__device__ __forceinline__ u64 fma2(u64 a, u64 b, u64 c) {
    u64 d; asm("fma.rn.f32x2 %0, %1, %2, %3;" : "=l"(d) : "l"(a), "l"(b), "l"(c)); return d;
}

// ---------------- scratch (static device globals; no allocation) -------------
__device__ float g_Rpart[Bz * KSsplit * Cc * Cc];   // 16 MB split-K partials
__device__ float g_R[Bz * Cc * Cc];                 // R = B B^T  per batch
__device__ float g_s[Bz * Cc];                      // row sums of b image
__device__ float g_gs[Bz * Cii];                    // g_w @ s
__device__ float g_ps2[Bz * Cii];                   // phi_w @ s + N*phi_b
__device__ float g_U[Bz * Cii * Cc];                // g_w @ R
__device__ float g_S[Bz * Cii * Cii];               // G Phi^T
__device__ float g_T[Bz * Cc * Cii];                // W_w @ S / N
__device__ float g_Q[Bz * Cc * Cc];                 // T @ theta_w
__device__ float g_dp[Bz * Cc];                     // folded bias (BN included)
__device__ float g_alpha[Cc];                       // BN scale

// smem tile geometry (transposed k-major tiles, pads keep LDS.128 16B-aligned)
#define APAD 68     // 64-row tile, stride 68 floats (272B, 16B-aligned)
#define BPAD 132    // 128-col tile, stride 132 floats (528B, 16B-aligned)
#define ABUF (32 * APAD)
#define BBUF (32 * BPAD)
#define SMEM_BYTES ((2 * ABUF + 2 * BBUF) * 4)   // 51200

// ---------------- row sums of b: s[b][c] = sum_n b[b,c,n] --------------------
__global__ __launch_bounds__(128) void k_rowsum(const float* __restrict__ bimg) {
    int bc = blockIdx.x;
    const float* row = bimg + (size_t)bc * Nn;
    float sum = 0.f;
    for (int i = threadIdx.x * 4; i < Nn; i += 128 * 4) {
        float4 v = *(const float4*)&row[i];
        sum += v.x + v.y + v.z + v.w;
    }
    #pragma unroll
    for (int o = 16; o > 0; o >>= 1) sum += __shfl_down_sync(0xffffffffu, sum, o);
    __shared__ float red[4];
    if ((threadIdx.x & 31) == 0) red[threadIdx.x >> 5] = sum;
    __syncthreads();
    if (threadIdx.x == 0) g_s[bc] = red[0] + red[1] + red[2] + red[3];
}

// ---------------- gs = g_w @ s ; ps2 = phi_w @ s + N*phi_b -------------------
__global__ __launch_bounds__(256) void k_gsps(const float* __restrict__ gw,
                                              const float* __restrict__ phiw,
                                              const float* __restrict__ phib) {
    int b = blockIdx.x;
    int tid = threadIdx.x;
    __shared__ float ssh[Cc];
    ssh[tid] = g_s[b * Cc + tid];
    __syncthreads();
    if (tid < Cii) {
        float acc = 0.f;
        for (int c = 0; c < Cc; c++) acc += gw[tid * Cc + c] * ssh[c];
        g_gs[b * Cii + tid] = acc;
    } else {
        int i = tid - Cii;
        float acc = 0.f;
        for (int c = 0; c < Cc; c++) acc += phiw[i * Cc + c] * ssh[c];
        g_ps2[b * Cii + i] = acc + (float)Nn * phib[i];
    }
}

// ---------------- shared inner product micro-kernel --------------------------
// Asm: [32][APAD] k-major 64-row operand; Bsn: [32][BPAD] k-major 128-col operand
__device__ __forceinline__ void mm_compute(const float* __restrict__ Asm,
                                           const float* __restrict__ Bsn,
                                           int warp, int lane, u64 acc[8][2]) {
    #pragma unroll 8
    for (int k = 0; k < 32; k++) {
        ulonglong2 bv = *(const ulonglong2*)&Bsn[k * BPAD + lane * 4];
        float4 a0 = *(const float4*)&Asm[k * APAD + warp * 8];
        float4 a1 = *(const float4*)&Asm[k * APAD + warp * 8 + 4];
        u64 ad;
        ad = pack2(a0.x, a0.x); acc[0][0] = fma2(ad, bv.x, acc[0][0]); acc[0][1] = fma2(ad, bv.y, acc[0][1]);
        ad = pack2(a0.y, a0.y); acc[1][0] = fma2(ad, bv.x, acc[1][0]); acc[1][1] = fma2(ad, bv.y, acc[1][1]);
        ad = pack2(a0.z, a0.z); acc[2][0] = fma2(ad, bv.x, acc[2][0]); acc[2][1] = fma2(ad, bv.y, acc[2][1]);
        ad = pack2(a0.w, a0.w); acc[3][0] = fma2(ad, bv.x, acc[3][0]); acc[3][1] = fma2(ad, bv.y, acc[3][1]);
        ad = pack2(a1.x, a1.x); acc[4][0] = fma2(ad, bv.x, acc[4][0]); acc[4][1] = fma2(ad, bv.y, acc[4][1]);
        ad = pack2(a1.y, a1.y); acc[5][0] = fma2(ad, bv.x, acc[5][0]); acc[5][1] = fma2(ad, bv.y, acc[5][1]);
        ad = pack2(a1.z, a1.z); acc[6][0] = fma2(ad, bv.x, acc[6][0]); acc[6][1] = fma2(ad, bv.y, acc[6][1]);
        ad = pack2(a1.w, a1.w); acc[7][0] = fma2(ad, bv.x, acc[7][0]); acc[7][1] = fma2(ad, bv.y, acc[7][1]);
    }
}

// ---------------- split-K SYRK: R_part[b,ks] = B[:,kslice] B[:,kslice]^T -----
// grid (4, 2, Bz*KSsplit), 256 threads; tile 64(i) x 128(j); warp-strip 8 rows,
// lane covers 4 contiguous j (conflict-free LDS.128). Double-buffered smem,
// register-staged global prefetch.
__global__ __launch_bounds__(256) void k_syrk(const float* __restrict__ bimg) {
    extern __shared__ __align__(16) float sm[];
    float* Asm = sm;                 // 2 * ABUF
    float* Bsn = sm + 2 * ABUF;      // 2 * BBUF
    int ti = blockIdx.x * 64;
    int tj = blockIdx.y * 128;
    int bz = blockIdx.z >> 4;
    int ks = blockIdx.z & (KSsplit - 1);
    const float* Bb = bimg + (size_t)bz * Cc * Nn;
    int tid = threadIdx.x;
    int lane = tid & 31, warp = tid >> 5;
    int k0 = ks * KPB;

    float4 va[2], vb[4];
    u64 acc[8][2] = {};

    // element mappings (constant per thread)
    int ar[2], ak[2], br[4], bk[4];
    #pragma unroll
    for (int l = 0; l < 2; l++) { int e = tid + l * 256; ar[l] = e >> 3; ak[l] = (e & 7) * 4; }
    #pragma unroll
    for (int l = 0; l < 4; l++) { int e = tid + l * 256; br[l] = e >> 3; bk[l] = (e & 7) * 4; }

    #define SY_LOAD(t) do { \
        int kb = k0 + (t) * 32; \
        _Pragma("unroll") for (int l = 0; l < 2; l++) \
            va[l] = *(const float4*)&Bb[(size_t)(ti + ar[l]) * Nn + kb + ak[l]]; \
        _Pragma("unroll") for (int l = 0; l < 4; l++) \
            vb[l] = *(const float4*)&Bb[(size_t)(tj + br[l]) * Nn + kb + bk[l]]; \
    } while (0)

    #define SY_STORE(buf) do { \
        _Pragma("unroll") for (int l = 0; l < 2; l++) { \
            float tv[4]; *(float4*)tv = va[l]; \
            _Pragma("unroll") for (int q = 0; q < 4; q++) \
                Asm[(buf) * ABUF + (ak[l] + q) * APAD + ar[l]] = tv[q]; \
        } \
        _Pragma("unroll") for (int l = 0; l < 4; l++) { \
            float tv[4]; *(float4*)tv = vb[l]; \
            _Pragma("unroll") for (int q = 0; q < 4; q++) \
                Bsn[(buf) * BBUF + (bk[l] + q) * BPAD + br[l]] = tv[q]; \
        } \
    } while (0)

    SY_LOAD(0);
    SY_STORE(0);
    __syncthreads();
    #pragma unroll 1
    for (int t = 0; t < KPB / 32; t++) {
        if (t + 1 < KPB / 32) SY_LOAD(t + 1);
        mm_compute(&Asm[(t & 1) * ABUF], &Bsn[(t & 1) * BBUF], warp, lane, acc);
        if (t + 1 < KPB / 32) {
            __syncthreads();
            SY_STORE((t + 1) & 1);
            __syncthreads();
        }
    }
    #undef SY_LOAD
    #undef SY_STORE

    float* Rp = g_Rpart + (size_t)(bz * KSsplit + ks) * Cc * Cc;
    #pragma unroll
    for (int i = 0; i < 8; i++) {
        int ci = ti + warp * 8 + i;
        float2 p0 = unpack2(acc[i][0]), p1 = unpack2(acc[i][1]);
        *(float4*)&Rp[(size_t)ci * Cc + tj + lane * 4] = make_float4(p0.x, p0.y, p1.x, p1.y);
    }
}

// ---------------- reduce split-K partials (float4) ---------------------------
__global__ __launch_bounds__(256) void k_reduceR() {
    int e = (blockIdx.x * 256 + threadIdx.x) * 4;  // < Bz*Cc*Cc
    int b = e >> 16;
    int r = e & 65535;
    float4 sum = make_float4(0.f, 0.f, 0.f, 0.f);
    #pragma unroll
    for (int ks = 0; ks < KSsplit; ks++) {
        float4 v = *(const float4*)&g_Rpart[(size_t)(b * KSsplit + ks) * Cc * Cc + r];
        sum.x += v.x; sum.y += v.y; sum.z += v.z; sum.w += v.w;
    }
    *(float4*)&g_R[e] = sum;
}

// ---------------- generic small batched GEMM (32x32 tiles) -------------------
__global__ __launch_bounds__(256) void k_gemm32(
    const float* __restrict__ A, long long sA,
    const float* __restrict__ B, long long sB,
    float* __restrict__ C, long long sC,
    int M, int N, int K, int BT, float scale,
    const float* __restrict__ r1a, long long s1a,
    const float* __restrict__ r1b, long long s1b,
    const float* __restrict__ r2a, long long s2a,
    const float* __restrict__ r2b, long long s2b)
{
    int m0 = blockIdx.x * 32, n0 = blockIdx.y * 32, bz = blockIdx.z;
    A += (size_t)bz * sA; B += (size_t)bz * sB; C += (size_t)bz * sC;
    __shared__ float As[32][33], Bs[32][33];
    int tid = threadIdx.x, tx = tid & 15, ty = tid >> 4;
    float acc00 = 0.f, acc01 = 0.f, acc10 = 0.f, acc11 = 0.f;
    for (int k0 = 0; k0 < K; k0 += 32) {
        #pragma unroll
        for (int l = 0; l < 4; l++) {
            int idx = tid + l * 256;
            int r = idx >> 5, k = idx & 31;
            As[k][r] = A[(size_t)(m0 + r) * K + k0 + k];
            if (!BT) Bs[r][k] = B[(size_t)(k0 + r) * N + n0 + k];
            else     Bs[k][r] = B[(size_t)(n0 + r) * K + k0 + k];
        }
        __syncthreads();
        #pragma unroll
        for (int k = 0; k < 32; k++) {
            float a0 = As[k][ty * 2], a1 = As[k][ty * 2 + 1];
            float b0 = Bs[k][tx * 2], b1 = Bs[k][tx * 2 + 1];
            acc00 += a0 * b0; acc01 += a0 * b1;
            acc10 += a1 * b0; acc11 += a1 * b1;
        }
        __syncthreads();
    }
    float e[2][2] = {{acc00, acc01}, {acc10, acc11}};
    #pragma unroll
    for (int ii = 0; ii < 2; ii++)
        #pragma unroll
        for (int jj = 0; jj < 2; jj++) {
            int m = m0 + ty * 2 + ii, n = n0 + tx * 2 + jj;
            float v = e[ii][jj] * scale;
            if (r1a)
                v += r1a[(size_t)bz * s1a + m] * r1b[(size_t)bz * s1b + n]
                   + r2a[(size_t)bz * s2a + m] * r2b[(size_t)bz * s2b + n];
            C[(size_t)m * N + n] = v;
        }
}

// ---------------- fold theta_b + BN into per-(b,c) bias & alpha --------------
__global__ __launch_bounds__(256) void k_dvec(
    const float* __restrict__ theta_b, const float* __restrict__ gamma,
    const float* __restrict__ beta, const float* __restrict__ mean,
    const float* __restrict__ var)
{
    int b = blockIdx.x, c = threadIdx.x;
    const float* Trow = g_T + ((size_t)b * Cc + c) * Cii;
    float d = 0.f;
    for (int i = 0; i < Cii; i++) d += Trow[i] * theta_b[i];
    float al = gamma[c] * rsqrtf(var[c] + 1e-5f);
    g_dp[b * Cc + c] = al * (d - mean[c]) + beta[c];
    if (b == 0) g_alpha[c] = al;
}

// ---------------- final: out[b] = alpha .* (Q[b] @ A[b]) + dp ----------------
// grid (4, 32, Bz); tile 64(c) x 128(n); K=256. Q transposed tile, A natural.
__global__ __launch_bounds__(256) void k_out(const float* __restrict__ aimg,
                                             float* __restrict__ out)
{
    extern __shared__ __align__(16) float sm[];
    float* Qs  = sm;                 // 2 * ABUF (64-row operand, k-major)
    float* Asn = sm + 2 * ABUF;      // 2 * BBUF (128-col operand, k-major)
    int tc = blockIdx.x * 64;
    int tn = blockIdx.y * 128;
    int bz = blockIdx.z;
    const float* Ab = aimg + (size_t)bz * Cc * Nn;
    const float* Qb = g_Q + (size_t)bz * Cc * Cc;
    int tid = threadIdx.x;
    int lane = tid & 31, warp = tid >> 5;

    float4 vq[2], va[4];
    u64 acc[8][2] = {};

    int qr[2], qk[2], akr[4], anq[4];
    #pragma unroll
    for (int l = 0; l < 2; l++) { int e = tid + l * 256; qr[l] = e >> 3; qk[l] = (e & 7) * 4; }
    #pragma unroll
    for (int l = 0; l < 4; l++) { int e = tid + l * 256; akr[l] = e >> 5; anq[l] = (e & 31) * 4; }

    #define FO_LOAD(t) do { \
        int kb = (t) * 32; \
        _Pragma("unroll") for (int l = 0; l < 2; l++) \
            vq[l] = *(const float4*)&Qb[(size_t)(tc + qr[l]) * Cc + kb + qk[l]]; \
        _Pragma("unroll") for (int l = 0; l < 4; l++) \
            va[l] = *(const float4*)&Ab[(size_t)(kb + akr[l]) * Nn + tn + anq[l]]; \
    } while (0)

    #define FO_STORE(buf) do { \
        _Pragma("unroll") for (int l = 0; l < 2; l++) { \
            float tv[4]; *(float4*)tv = vq[l]; \
            _Pragma("unroll") for (int q = 0; q < 4; q++) \
                Qs[(buf) * ABUF + (qk[l] + q) * APAD + qr[l]] = tv[q]; \
        } \
        _Pragma("unroll") for (int l = 0; l < 4; l++) \
            *(float4*)&Asn[(buf) * BBUF + akr[l] * BPAD + anq[l]] = va[l]; \
    } while (0)

    FO_LOAD(0);
    FO_STORE(0);
    __syncthreads();
    #pragma unroll 1
    for (int t = 0; t < Cc / 32; t++) {
        if (t + 1 < Cc / 32) FO_LOAD(t + 1);
        mm_compute(&Qs[(t & 1) * ABUF], &Asn[(t & 1) * BBUF], warp, lane, acc);
        if (t + 1 < Cc / 32) {
            __syncthreads();
            FO_STORE((t + 1) & 1);
            __syncthreads();
        }
    }
    #undef FO_LOAD
    #undef FO_STORE

    float* outb = out + (size_t)bz * Cc * Nn;
    #pragma unroll
    for (int i = 0; i < 8; i++) {
        int c = tc + warp * 8 + i;
        float al = g_alpha[c];
        float dpv = g_dp[bz * Cc + c];
        float2 p0 = unpack2(acc[i][0]), p1 = unpack2(acc[i][1]);
        *(float4*)&outb[(size_t)c * Nn + tn + lane * 4] =
            make_float4(al * p0.x + dpv, al * p0.y + dpv, al * p1.x + dpv, al * p1.y + dpv);
    }
}

// -----------------------------------------------------------------------------
extern "C" void kernel_launch(void* const* d_in, const int* in_sizes, int n_in,
                              void* d_out, int out_size) {
    (void)in_sizes; (void)n_in; (void)out_size;
    const float* a       = (const float*)d_in[0];
    const float* bimg    = (const float*)d_in[1];
    const float* theta_w = (const float*)d_in[2];
    const float* theta_b = (const float*)d_in[3];
    const float* phi_w   = (const float*)d_in[4];
    const float* phi_b   = (const float*)d_in[5];
    const float* g_wp    = (const float*)d_in[6];
    const float* g_bp    = (const float*)d_in[7];
    const float* W_wp    = (const float*)d_in[8];
    const float* gamma   = (const float*)d_in[9];
    const float* beta    = (const float*)d_in[10];
    const float* mean    = (const float*)d_in[11];
    const float* var     = (const float*)d_in[12];

    static int attr_done = 0;
    if (!attr_done) {
        cudaFuncSetAttribute(k_syrk, cudaFuncAttributeMaxDynamicSharedMemorySize, SMEM_BYTES);
        cudaFuncSetAttribute(k_out,  cudaFuncAttributeMaxDynamicSharedMemorySize, SMEM_BYTES);
        attr_done = 1;
    }

    float *pR, *pU, *pS, *pT, *pQ, *pGs, *pPs2;
    cudaGetSymbolAddress((void**)&pR,   g_R);
    cudaGetSymbolAddress((void**)&pU,   g_U);
    cudaGetSymbolAddress((void**)&pS,   g_S);
    cudaGetSymbolAddress((void**)&pT,   g_T);
    cudaGetSymbolAddress((void**)&pQ,   g_Q);
    cudaGetSymbolAddress((void**)&pGs,  g_gs);
    cudaGetSymbolAddress((void**)&pPs2, g_ps2);

    k_rowsum<<<Bz * Cc, 128>>>(bimg);
    k_gsps<<<Bz, 256>>>(g_wp, phi_w, phi_b);
    k_syrk<<<dim3(4, 2, Bz * KSsplit), 256, SMEM_BYTES>>>(bimg);
    k_reduceR<<<(Bz * Cc * Cc) / 1024, 256>>>();

    // U[b] = g_w @ R[b]
    k_gemm32<<<dim3(Cii / 32, Cc / 32, Bz), 256>>>(
        g_wp, 0, pR, (long long)Cc * Cc, pU, (long long)Cii * Cc,
        Cii, Cc, Cc, 0, 1.f,
        nullptr, 0, nullptr, 0, nullptr, 0, nullptr, 0);
    // S[b] = U[b] @ phi_w^T + gs*phib^T + gb*ps2^T
    k_gemm32<<<dim3(Cii / 32, Cii / 32, Bz), 256>>>(
        pU, (long long)Cii * Cc, phi_w, 0, pS, (long long)Cii * Cii,
        Cii, Cii, Cc, 1, 1.f,
        pGs, Cii, phi_b, 0, g_bp, 0, pPs2, Cii);
    // T[b] = W_w @ S[b] / N
    k_gemm32<<<dim3(Cc / 32, Cii / 32, Bz), 256>>>(
        W_wp, 0, pS, (long long)Cii * Cii, pT, (long long)Cc * Cii,
        Cc, Cii, Cii, 0, 1.f / (float)Nn,
        nullptr, 0, nullptr, 0, nullptr, 0, nullptr, 0);
    // Q[b] = T[b] @ theta_w
    k_gemm32<<<dim3(Cc / 32, Cc / 32, Bz), 256>>>(
        pT, (long long)Cc * Cii, theta_w, 0, pQ, (long long)Cc * Cc,
        Cc, Cc, Cii, 0, 1.f,
        nullptr, 0, nullptr, 0, nullptr, 0, nullptr, 0);

    k_dvec<<<Bz, 256>>>(theta_b, gamma, beta, mean, var);
    k_out<<<dim3(Cc / 64, Nn / 128, Bz), 256, SMEM_BYTES>>>(a, (float*)d_out);
}

// round 4
// speedup vs baseline: 1.3172x; 1.0154x over previous
#include <cuda_runtime.h>

#define Bz 4
#define Cc 256
#define Cii 128
#define Nn 4096
#define KSsplit 16
#define KPB (Nn / KSsplit)   // 256 K per split block

typedef unsigned long long u64;

__device__ __forceinline__ u64 pack2(float lo, float hi) {
    u64 r; asm("mov.b64 %0, {%1,%2};" : "=l"(r) : "f"(lo), "f"(hi)); return r;
}
__device__ __forceinline__ float2 unpack2(u64 v) {
    float2 f; asm("mov.b64 {%0,%1}, %2;" : "=f"(f.x), "=f"(f.y) : "l"(v)); return f;
}
__device__ __forceinline__ u64 fma2(u64 a, u64 b, u64 c) {
    u64 d; asm("fma.rn.f32x2 %0, %1, %2, %3;" : "=l"(d) : "l"(a), "l"(b), "l"(c)); return d;
}

// ---------------- scratch (static device globals; no allocation) -------------
__device__ float g_R[Bz * Cc * Cc];                 // R = B B^T  per batch (atomically reduced)
__device__ float g_s[Bz * Cc];                      // row sums of b image (atomically reduced)
__device__ float g_gs[Bz * Cii];                    // g_w @ s
__device__ float g_ps2[Bz * Cii];                   // phi_w @ s + N*phi_b
__device__ float g_U[Bz * Cii * Cc];                // g_w @ R
__device__ float g_S[Bz * Cii * Cii];               // G Phi^T
__device__ float g_T[Bz * Cc * Cii];                // W_w @ S / N
__device__ float g_Q[Bz * Cc * Cc];                 // T @ theta_w
__device__ float g_dp[Bz * Cc];                     // folded bias (BN included)
__device__ float g_alpha[Cc];                       // BN scale

// smem tile geometry (transposed k-major tiles, pads keep LDS.128 16B-aligned)
#define APAD 68     // 64-row tile, stride 68 floats
#define BPAD 132    // 128-col tile, stride 132 floats
#define ABUF (32 * APAD)
#define BBUF (32 * BPAD)
#define SMEM_BYTES ((2 * ABUF + 2 * BBUF) * 4)   // 51200

// ---------------- zero the atomic-reduce targets ------------------------------
__global__ __launch_bounds__(256) void k_zero() {
    int i = blockIdx.x * 256 + threadIdx.x;
    ((float4*)g_R)[i] = make_float4(0.f, 0.f, 0.f, 0.f);
    if (i < (Bz * Cc) / 4) ((float4*)g_s)[i] = make_float4(0.f, 0.f, 0.f, 0.f);
}

// ---------------- gs = g_w @ s ; ps2 = phi_w @ s + N*phi_b -------------------
__global__ __launch_bounds__(256) void k_gsps(const float* __restrict__ gw,
                                              const float* __restrict__ phiw,
                                              const float* __restrict__ phib) {
    int b = blockIdx.x;
    int tid = threadIdx.x;
    __shared__ float ssh[Cc];
    ssh[tid] = g_s[b * Cc + tid];
    __syncthreads();
    if (tid < Cii) {
        float acc = 0.f;
        for (int c = 0; c < Cc; c++) acc += gw[tid * Cc + c] * ssh[c];
        g_gs[b * Cii + tid] = acc;
    } else {
        int i = tid - Cii;
        float acc = 0.f;
        for (int c = 0; c < Cc; c++) acc += phiw[i * Cc + c] * ssh[c];
        g_ps2[b * Cii + i] = acc + (float)Nn * phib[i];
    }
}

// ---------------- shared inner product micro-kernel --------------------------
__device__ __forceinline__ void mm_compute(const float* __restrict__ Asm,
                                           const float* __restrict__ Bsn,
                                           int warp, int lane, u64 acc[8][2]) {
    #pragma unroll 8
    for (int k = 0; k < 32; k++) {
        ulonglong2 bv = *(const ulonglong2*)&Bsn[k * BPAD + lane * 4];
        float4 a0 = *(const float4*)&Asm[k * APAD + warp * 8];
        float4 a1 = *(const float4*)&Asm[k * APAD + warp * 8 + 4];
        u64 ad;
        ad = pack2(a0.x, a0.x); acc[0][0] = fma2(ad, bv.x, acc[0][0]); acc[0][1] = fma2(ad, bv.y, acc[0][1]);
        ad = pack2(a0.y, a0.y); acc[1][0] = fma2(ad, bv.x, acc[1][0]); acc[1][1] = fma2(ad, bv.y, acc[1][1]);
        ad = pack2(a0.z, a0.z); acc[2][0] = fma2(ad, bv.x, acc[2][0]); acc[2][1] = fma2(ad, bv.y, acc[2][1]);
        ad = pack2(a0.w, a0.w); acc[3][0] = fma2(ad, bv.x, acc[3][0]); acc[3][1] = fma2(ad, bv.y, acc[3][1]);
        ad = pack2(a1.x, a1.x); acc[4][0] = fma2(ad, bv.x, acc[4][0]); acc[4][1] = fma2(ad, bv.y, acc[4][1]);
        ad = pack2(a1.y, a1.y); acc[5][0] = fma2(ad, bv.x, acc[5][0]); acc[5][1] = fma2(ad, bv.y, acc[5][1]);
        ad = pack2(a1.z, a1.z); acc[6][0] = fma2(ad, bv.x, acc[6][0]); acc[6][1] = fma2(ad, bv.y, acc[6][1]);
        ad = pack2(a1.w, a1.w); acc[7][0] = fma2(ad, bv.x, acc[7][0]); acc[7][1] = fma2(ad, bv.y, acc[7][1]);
    }
}

// ---------------- split-K SYRK with atomic reduce + fused row sums -----------
// grid (4, 2, Bz*KSsplit), 256 threads; tile 64(i) x 128(j).
// 3-stage pipeline: compute(t); store(t+1); sync; load(t+2) — one sync/iter.
__global__ __launch_bounds__(256) void k_syrk(const float* __restrict__ bimg) {
    extern __shared__ __align__(16) float sm[];
    float* Asm = sm;
    float* Bsn = sm + 2 * ABUF;
    int ti = blockIdx.x * 64;
    int tj = blockIdx.y * 128;
    int bz = blockIdx.z >> 4;
    int ks = blockIdx.z & (KSsplit - 1);
    const float* Bb = bimg + (size_t)bz * Cc * Nn;
    int tid = threadIdx.x;
    int lane = tid & 31, warp = tid >> 5;
    int k0 = ks * KPB;

    float4 va[2], vb[4];
    u64 acc[8][2] = {};
    float rs0 = 0.f, rs1 = 0.f;

    int ar[2], ak[2], br[4], bk[4];
    #pragma unroll
    for (int l = 0; l < 2; l++) { int e = tid + l * 256; ar[l] = e >> 3; ak[l] = (e & 7) * 4; }
    #pragma unroll
    for (int l = 0; l < 4; l++) { int e = tid + l * 256; br[l] = e >> 3; bk[l] = (e & 7) * 4; }

    #define SY_LOAD(t) do { \
        int kb = k0 + (t) * 32; \
        _Pragma("unroll") for (int l = 0; l < 2; l++) \
            va[l] = *(const float4*)&Bb[(size_t)(ti + ar[l]) * Nn + kb + ak[l]]; \
        _Pragma("unroll") for (int l = 0; l < 4; l++) \
            vb[l] = *(const float4*)&Bb[(size_t)(tj + br[l]) * Nn + kb + bk[l]]; \
    } while (0)

    #define SY_STORE(buf) do { \
        _Pragma("unroll") for (int l = 0; l < 2; l++) { \
            float tv[4]; *(float4*)tv = va[l]; \
            _Pragma("unroll") for (int q = 0; q < 4; q++) \
                Asm[(buf) * ABUF + (ak[l] + q) * APAD + ar[l]] = tv[q]; \
        } \
        rs0 += va[0].x + va[0].y + va[0].z + va[0].w; \
        rs1 += va[1].x + va[1].y + va[1].z + va[1].w; \
        _Pragma("unroll") for (int l = 0; l < 4; l++) { \
            float tv[4]; *(float4*)tv = vb[l]; \
            _Pragma("unroll") for (int q = 0; q < 4; q++) \
                Bsn[(buf) * BBUF + (bk[l] + q) * BPAD + br[l]] = tv[q]; \
        } \
    } while (0)

    const int T = KPB / 32;   // 8
    SY_LOAD(0);
    SY_STORE(0);
    SY_LOAD(1);
    __syncthreads();
    #pragma unroll 1
    for (int t = 0; t < T; t++) {
        mm_compute(&Asm[(t & 1) * ABUF], &Bsn[(t & 1) * BBUF], warp, lane, acc);
        if (t + 1 < T) SY_STORE((t + 1) & 1);
        __syncthreads();
        if (t + 2 < T) SY_LOAD(t + 2);
    }
    #undef SY_LOAD
    #undef SY_STORE

    // fused row sums of b image (each (row,k) covered exactly once by tj==0 blocks)
    if (blockIdx.y == 0) {
        atomicAdd(&g_s[bz * Cc + ti + ar[0]], rs0);
        atomicAdd(&g_s[bz * Cc + ti + ar[1]], rs1);
    }

    // atomic split-K reduce straight into g_R (L2-resident, 1 MB)
    float* Rb = g_R + (size_t)bz * Cc * Cc;
    #pragma unroll
    for (int i = 0; i < 8; i++) {
        int ci = ti + warp * 8 + i;
        float2 p0 = unpack2(acc[i][0]), p1 = unpack2(acc[i][1]);
        float* dst = &Rb[(size_t)ci * Cc + tj + lane * 4];
        atomicAdd(dst + 0, p0.x);
        atomicAdd(dst + 1, p0.y);
        atomicAdd(dst + 2, p1.x);
        atomicAdd(dst + 3, p1.y);
    }
}

// ---------------- generic small batched GEMM (32x32 tiles) -------------------
__global__ __launch_bounds__(256) void k_gemm32(
    const float* __restrict__ A, long long sA,
    const float* __restrict__ B, long long sB,
    float* __restrict__ C, long long sC,
    int M, int N, int K, int BT, float scale,
    const float* __restrict__ r1a, long long s1a,
    const float* __restrict__ r1b, long long s1b,
    const float* __restrict__ r2a, long long s2a,
    const float* __restrict__ r2b, long long s2b)
{
    int m0 = blockIdx.x * 32, n0 = blockIdx.y * 32, bz = blockIdx.z;
    A += (size_t)bz * sA; B += (size_t)bz * sB; C += (size_t)bz * sC;
    __shared__ float As[32][33], Bs[32][33];
    int tid = threadIdx.x, tx = tid & 15, ty = tid >> 4;
    float acc00 = 0.f, acc01 = 0.f, acc10 = 0.f, acc11 = 0.f;
    for (int k0 = 0; k0 < K; k0 += 32) {
        #pragma unroll
        for (int l = 0; l < 4; l++) {
            int idx = tid + l * 256;
            int r = idx >> 5, k = idx & 31;
            As[k][r] = A[(size_t)(m0 + r) * K + k0 + k];
            if (!BT) Bs[r][k] = B[(size_t)(k0 + r) * N + n0 + k];
            else     Bs[k][r] = B[(size_t)(n0 + r) * K + k0 + k];
        }
        __syncthreads();
        #pragma unroll
        for (int k = 0; k < 32; k++) {
            float a0 = As[k][ty * 2], a1 = As[k][ty * 2 + 1];
            float b0 = Bs[k][tx * 2], b1 = Bs[k][tx * 2 + 1];
            acc00 += a0 * b0; acc01 += a0 * b1;
            acc10 += a1 * b0; acc11 += a1 * b1;
        }
        __syncthreads();
    }
    float e[2][2] = {{acc00, acc01}, {acc10, acc11}};
    #pragma unroll
    for (int ii = 0; ii < 2; ii++)
        #pragma unroll
        for (int jj = 0; jj < 2; jj++) {
            int m = m0 + ty * 2 + ii, n = n0 + tx * 2 + jj;
            float v = e[ii][jj] * scale;
            if (r1a)
                v += r1a[(size_t)bz * s1a + m] * r1b[(size_t)bz * s1b + n]
                   + r2a[(size_t)bz * s2a + m] * r2b[(size_t)bz * s2b + n];
            C[(size_t)m * N + n] = v;
        }
}

// ---------------- fold theta_b + BN into per-(b,c) bias & alpha --------------
__global__ __launch_bounds__(256) void k_dvec(
    const float* __restrict__ theta_b, const float* __restrict__ gamma,
    const float* __restrict__ beta, const float* __restrict__ mean,
    const float* __restrict__ var)
{
    int b = blockIdx.x, c = threadIdx.x;
    const float* Trow = g_T + ((size_t)b * Cc + c) * Cii;
    float d = 0.f;
    for (int i = 0; i < Cii; i++) d += Trow[i] * theta_b[i];
    float al = gamma[c] * rsqrtf(var[c] + 1e-5f);
    g_dp[b * Cc + c] = al * (d - mean[c]) + beta[c];
    if (b == 0) g_alpha[c] = al;
}

// ---------------- final: out[b] = alpha .* (Q[b] @ A[b]) + dp ----------------
// grid (4, 32, Bz); tile 64(c) x 128(n); K=256. Same 3-stage pipeline.
__global__ __launch_bounds__(256) void k_out(const float* __restrict__ aimg,
                                             float* __restrict__ out)
{
    extern __shared__ __align__(16) float sm[];
    float* Qs  = sm;
    float* Asn = sm + 2 * ABUF;
    int tc = blockIdx.x * 64;
    int tn = blockIdx.y * 128;
    int bz = blockIdx.z;
    const float* Ab = aimg + (size_t)bz * Cc * Nn;
    const float* Qb = g_Q + (size_t)bz * Cc * Cc;
    int tid = threadIdx.x;
    int lane = tid & 31, warp = tid >> 5;

    float4 vq[2], va[4];
    u64 acc[8][2] = {};

    int qr[2], qk[2], akr[4], anq[4];
    #pragma unroll
    for (int l = 0; l < 2; l++) { int e = tid + l * 256; qr[l] = e >> 3; qk[l] = (e & 7) * 4; }
    #pragma unroll
    for (int l = 0; l < 4; l++) { int e = tid + l * 256; akr[l] = e >> 5; anq[l] = (e & 31) * 4; }

    #define FO_LOAD(t) do { \
        int kb = (t) * 32; \
        _Pragma("unroll") for (int l = 0; l < 2; l++) \
            vq[l] = *(const float4*)&Qb[(size_t)(tc + qr[l]) * Cc + kb + qk[l]]; \
        _Pragma("unroll") for (int l = 0; l < 4; l++) \
            va[l] = *(const float4*)&Ab[(size_t)(kb + akr[l]) * Nn + tn + anq[l]]; \
    } while (0)

    #define FO_STORE(buf) do { \
        _Pragma("unroll") for (int l = 0; l < 2; l++) { \
            float tv[4]; *(float4*)tv = vq[l]; \
            _Pragma("unroll") for (int q = 0; q < 4; q++) \
                Qs[(buf) * ABUF + (qk[l] + q) * APAD + qr[l]] = tv[q]; \
        } \
        _Pragma("unroll") for (int l = 0; l < 4; l++) \
            *(float4*)&Asn[(buf) * BBUF + akr[l] * BPAD + anq[l]] = va[l]; \
    } while (0)

    const int T = Cc / 32;   // 8
    FO_LOAD(0);
    FO_STORE(0);
    FO_LOAD(1);
    __syncthreads();
    #pragma unroll 1
    for (int t = 0; t < T; t++) {
        mm_compute(&Qs[(t & 1) * ABUF], &Asn[(t & 1) * BBUF], warp, lane, acc);
        if (t + 1 < T) FO_STORE((t + 1) & 1);
        __syncthreads();
        if (t + 2 < T) FO_LOAD(t + 2);
    }
    #undef FO_LOAD
    #undef FO_STORE

    float* outb = out + (size_t)bz * Cc * Nn;
    #pragma unroll
    for (int i = 0; i < 8; i++) {
        int c = tc + warp * 8 + i;
        float al = g_alpha[c];
        float dpv = g_dp[bz * Cc + c];
        float2 p0 = unpack2(acc[i][0]), p1 = unpack2(acc[i][1]);
        *(float4*)&outb[(size_t)c * Nn + tn + lane * 4] =
            make_float4(al * p0.x + dpv, al * p0.y + dpv, al * p1.x + dpv, al * p1.y + dpv);
    }
}

// -----------------------------------------------------------------------------
extern "C" void kernel_launch(void* const* d_in, const int* in_sizes, int n_in,
                              void* d_out, int out_size) {
    (void)in_sizes; (void)n_in; (void)out_size;
    const float* a       = (const float*)d_in[0];
    const float* bimg    = (const float*)d_in[1];
    const float* theta_w = (const float*)d_in[2];
    const float* theta_b = (const float*)d_in[3];
    const float* phi_w   = (const float*)d_in[4];
    const float* phi_b   = (const float*)d_in[5];
    const float* g_wp    = (const float*)d_in[6];
    const float* g_bp    = (const float*)d_in[7];
    const float* W_wp    = (const float*)d_in[8];
    const float* gamma   = (const float*)d_in[9];
    const float* beta    = (const float*)d_in[10];
    const float* mean    = (const float*)d_in[11];
    const float* var     = (const float*)d_in[12];

    static int attr_done = 0;
    if (!attr_done) {
        cudaFuncSetAttribute(k_syrk, cudaFuncAttributeMaxDynamicSharedMemorySize, SMEM_BYTES);
        cudaFuncSetAttribute(k_out,  cudaFuncAttributeMaxDynamicSharedMemorySize, SMEM_BYTES);
        attr_done = 1;
    }

    float *pR, *pU, *pS, *pT, *pQ, *pGs, *pPs2;
    cudaGetSymbolAddress((void**)&pR,   g_R);
    cudaGetSymbolAddress((void**)&pU,   g_U);
    cudaGetSymbolAddress((void**)&pS,   g_S);
    cudaGetSymbolAddress((void**)&pT,   g_T);
    cudaGetSymbolAddress((void**)&pQ,   g_Q);
    cudaGetSymbolAddress((void**)&pGs,  g_gs);
    cudaGetSymbolAddress((void**)&pPs2, g_ps2);

    k_zero<<<(Bz * Cc * Cc / 4) / 256, 256>>>();
    k_syrk<<<dim3(4, 2, Bz * KSsplit), 256, SMEM_BYTES>>>(bimg);
    k_gsps<<<Bz, 256>>>(g_wp, phi_w, phi_b);

    // U[b] = g_w @ R[b]
    k_gemm32<<<dim3(Cii / 32, Cc / 32, Bz), 256>>>(
        g_wp, 0, pR, (long long)Cc * Cc, pU, (long long)Cii * Cc,
        Cii, Cc, Cc, 0, 1.f,
        nullptr, 0, nullptr, 0, nullptr, 0, nullptr, 0);
    // S[b] = U[b] @ phi_w^T + gs*phib^T + gb*ps2^T
    k_gemm32<<<dim3(Cii / 32, Cii / 32, Bz), 256>>>(
        pU, (long long)Cii * Cc, phi_w, 0, pS, (long long)Cii * Cii,
        Cii, Cii, Cc, 1, 1.f,
        pGs, Cii, phi_b, 0, g_bp, 0, pPs2, Cii);
    // T[b] = W_w @ S[b] / N
    k_gemm32<<<dim3(Cc / 32, Cii / 32, Bz), 256>>>(
        W_wp, 0, pS, (long long)Cii * Cii, pT, (long long)Cc * Cii,
        Cc, Cii, Cii, 0, 1.f / (float)Nn,
        nullptr, 0, nullptr, 0, nullptr, 0, nullptr, 0);
    // Q[b] = T[b] @ theta_w
    k_gemm32<<<dim3(Cc / 32, Cc / 32, Bz), 256>>>(
        pT, (long long)Cc * Cii, theta_w, 0, pQ, (long long)Cc * Cc,
        Cc, Cc, Cii, 0, 1.f,
        nullptr, 0, nullptr, 0, nullptr, 0, nullptr, 0);

    k_dvec<<<Bz, 256>>>(theta_b, gamma, beta, mean, var);
    k_out<<<dim3(Cc / 64, Nn / 128, Bz), 256, SMEM_BYTES>>>(a, (float*)d_out);
}